// round 5
// baseline (speedup 1.0000x reference)
#include <cuda_runtime.h>

// DigitCaps dynamic routing, fused. B=64, R=6912, I=8, C=10, O=16, 3 iters.
//
//   k_transpose : x[B,R,I] -> xT[j=r*2+h][b] (float4 transposed)
//   k_pass<0>   : p=W^T x; acc += p;                 last CTA: out0=squash
//   k_pass<1>   : w=exp(p.out0); acc += w*p;         last CTA: out1=squash
//   k_pass<2>   : w=exp(p.(out0+out1)); acc += w*p;  last CTA: squash->d_out
//
// Warp = 16 bq-lanes x 2 o-halves; thread owns 4 b's x 8 o's. One warp-step
// covers all 64 b for one (c,r): 16 LDS.128 of W feed 160 fma2.
// W tile staged with one cp.async.bulk (mbarrier). Reduction buffer aliases
// the W tile. logits never materialized. Replay-clean state.

#define R_DIM 6912
#define B_DIM 64
#define C_DIM 10
#define R_BLK 64
#define NCTAS ((R_DIM / R_BLK) * C_DIM)   // 1080

typedef unsigned long long u64;

__device__ __align__(16) float g_xT[R_DIM * 2 * B_DIM * 4];   // [r*2+h][b] float4
__device__ __align__(16) float g_acc[C_DIM * B_DIM * 16];
__device__ __align__(16) float g_accw[C_DIM * B_DIM];
__device__ __align__(16) float g_out[2][C_DIM * B_DIM * 16];
__device__ unsigned g_ctr = 0;

__device__ __forceinline__ u64 pack2(float lo, float hi) {
    u64 r; asm("mov.b64 %0, {%1, %2};" : "=l"(r) : "f"(lo), "f"(hi)); return r;
}
__device__ __forceinline__ void unpack2(u64 v, float& lo, float& hi) {
    asm("mov.b64 {%0, %1}, %2;" : "=f"(lo), "=f"(hi) : "l"(v));
}
__device__ __forceinline__ u64 fma2(u64 a, u64 b, u64 c) {
    u64 d; asm("fma.rn.f32x2 %0, %1, %2, %3;" : "=l"(d) : "l"(a), "l"(b), "l"(c)); return d;
}
__device__ __forceinline__ u64 add2(u64 a, u64 b) {
    u64 d; asm("add.rn.f32x2 %0, %1, %2;" : "=l"(d) : "l"(a), "l"(b)); return d;
}
__device__ __forceinline__ unsigned smem_u32(const void* p) {
    return (unsigned)__cvta_generic_to_shared(p);
}

// x as float4 matrix [64][13824] -> [13824][64]
__global__ void k_transpose(const float4* __restrict__ x4) {
    __shared__ float4 tile[32][33];
    const int jb = blockIdx.x * 32;
    const int bb = blockIdx.y * 32;
    const int tx = threadIdx.x, ty = threadIdx.y;   // 32 x 8
    #pragma unroll
    for (int k = 0; k < 32; k += 8)
        tile[ty + k][tx] = x4[(size_t)(bb + ty + k) * (R_DIM * 2) + jb + tx];
    __syncthreads();
    float4* out4 = reinterpret_cast<float4*>(g_xT);
    #pragma unroll
    for (int k = 0; k < 32; k += 8)
        out4[(size_t)(jb + ty + k) * B_DIM + bb + tx] = tile[tx][ty + k];
}

// MODE 0: uniform; 1: w=exp(p.out0); 2: w=exp(p.(out0+out1))
template <int MODE>
__global__ void __launch_bounds__(256, 2)
k_pass(const float* __restrict__ Wg, float* __restrict__ dout) {
    const int c      = blockIdx.y;
    const int rblock = blockIdx.x * R_BLK;
    const int tid    = threadIdx.x;
    const int warp   = tid >> 5;                  // 0..7, each covers 8 r
    const int lane   = tid & 31;
    const int oh     = lane >> 4;                 // o-half
    const int bq     = lane & 15;                 // b base; owns bq + {0,16,32,48}

    __shared__ __align__(16) float sW[R_BLK * 128];   // 32 KB; aliased by sred after loop
    __shared__ float sredW[8][B_DIM];                 // 2 KB
    __shared__ __align__(8) unsigned long long s_mbar;
    __shared__ unsigned s_rank;
    float (*sred)[B_DIM][16] = reinterpret_cast<float (*)[B_DIM][16]>(sW); // [8][64][16]

    const unsigned mbar = smem_u32(&s_mbar);
    if (tid == 0)
        asm volatile("mbarrier.init.shared.b64 [%0], %1;" :: "r"(mbar), "r"(1u));
    __syncthreads();
    if (tid == 0) {
        asm volatile("mbarrier.arrive.expect_tx.shared.b64 _, [%0], %1;"
                     :: "r"(mbar), "r"(32768u) : "memory");
        const void* src = Wg + ((size_t)c * R_DIM + rblock) * 128;
        asm volatile("cp.async.bulk.shared::cluster.global.mbarrier::complete_tx::bytes "
                     "[%0], [%1], %2, [%3];"
                     :: "r"(smem_u32(sW)), "l"(src), "r"(32768u), "r"(mbar) : "memory");
    }

    // out vectors for 4 b's (o-half), loop-invariant — load while bulk copy flies
    u64 ov[4][4];
    if (MODE != 0) {
        #pragma unroll
        for (int j = 0; j < 4; j++) {
            const u64* p0 = reinterpret_cast<const u64*>(
                g_out[0] + (c * B_DIM + bq + j * 16) * 16 + oh * 8);
            #pragma unroll
            for (int t = 0; t < 4; t++) ov[j][t] = p0[t];
            if (MODE == 2) {
                const u64* p1 = reinterpret_cast<const u64*>(
                    g_out[1] + (c * B_DIM + bq + j * 16) * 16 + oh * 8);
                #pragma unroll
                for (int t = 0; t < 4; t++) ov[j][t] = add2(ov[j][t], p1[t]);
            }
        }
    }

    u64 acc[4][4];
    #pragma unroll
    for (int j = 0; j < 4; j++)
        #pragma unroll
        for (int t = 0; t < 4; t++) acc[j][t] = 0ull;
    float accw[4] = {0.0f, 0.0f, 0.0f, 0.0f};

    // wait for W tile
    asm volatile(
        "{\n\t.reg .pred P;\n"
        "WLP%=:\n\t"
        "mbarrier.try_wait.parity.shared.b64 P, [%0], 0;\n\t"
        "@!P bra WLP%=;\n\t}"
        :: "r"(mbar) : "memory");

    const float4* x4 = reinterpret_cast<const float4*>(g_xT);

    #pragma unroll 1
    for (int k = 0; k < 8; k++) {
        const int rl = warp * 8 + k;
        const int r  = rblock + rl;
        const ulonglong2* wp = reinterpret_cast<const ulonglong2*>(sW + rl * 128 + oh * 8);

        u64 p[4][4];
        #pragma unroll
        for (int j = 0; j < 4; j++)
            #pragma unroll
            for (int t = 0; t < 4; t++) p[j][t] = 0ull;

        #pragma unroll
        for (int h = 0; h < 2; h++) {
            float4 xv[4];
            #pragma unroll
            for (int j = 0; j < 4; j++)
                xv[j] = x4[(size_t)(r * 2 + h) * B_DIM + bq + j * 16];
            #pragma unroll
            for (int ii = 0; ii < 4; ii++) {
                const int i = h * 4 + ii;
                ulonglong2 wA = wp[i * 4 + 0];    // o-half floats 0..3
                ulonglong2 wB = wp[i * 4 + 1];    // o-half floats 4..7
                #pragma unroll
                for (int j = 0; j < 4; j++) {
                    float xs = (ii == 0) ? xv[j].x : (ii == 1) ? xv[j].y
                             : (ii == 2) ? xv[j].z : xv[j].w;
                    u64 xx = pack2(xs, xs);
                    p[j][0] = fma2(wA.x, xx, p[j][0]);
                    p[j][1] = fma2(wA.y, xx, p[j][1]);
                    p[j][2] = fma2(wB.x, xx, p[j][2]);
                    p[j][3] = fma2(wB.y, xx, p[j][3]);
                }
            }
        }

        if (MODE == 0) {
            #pragma unroll
            for (int j = 0; j < 4; j++)
                #pragma unroll
                for (int t = 0; t < 4; t++) acc[j][t] = add2(acc[j][t], p[j][t]);
        } else {
            #pragma unroll
            for (int j = 0; j < 4; j++) {
                u64 d = 0ull;
                #pragma unroll
                for (int t = 0; t < 4; t++) d = fma2(p[j][t], ov[j][t], d);
                float lo, hi; unpack2(d, lo, hi);
                float del = lo + hi;
                del += __shfl_xor_sync(0xffffffffu, del, 16);   // join o-halves
                del = fminf(del, 70.0f);
                float w = __expf(del);
                accw[j] += w;
                u64 w2 = pack2(w, w);
                #pragma unroll
                for (int t = 0; t < 4; t++) acc[j][t] = fma2(p[j][t], w2, acc[j][t]);
            }
        }
    }

    __syncthreads();   // all warps done reading sW; safe to alias as sred

    #pragma unroll
    for (int j = 0; j < 4; j++) {
        float2* s = reinterpret_cast<float2*>(&sred[warp][bq + j * 16][oh * 8]);
        #pragma unroll
        for (int t = 0; t < 4; t++) {
            float lo, hi; unpack2(acc[j][t], lo, hi);
            s[t] = make_float2(lo, hi);
        }
        if (MODE != 0 && oh == 0) sredW[warp][bq + j * 16] = accw[j];
    }
    __syncthreads();

    // fold 8 warps -> global atomics
    for (int idx = tid; idx < B_DIM * 16; idx += 256) {
        float v = 0.0f;
        #pragma unroll
        for (int w = 0; w < 8; w++) v += sred[w][0][idx];   // [w][b][o] flattened
        atomicAdd(&g_acc[c * (B_DIM * 16) + idx], v);
    }
    if (MODE != 0 && tid < B_DIM) {
        float v = 0.0f;
        #pragma unroll
        for (int w = 0; w < 8; w++) v += sredW[w][tid];
        atomicAdd(&g_accw[c * B_DIM + tid], v);
    }

    // ---- last CTA: squash inline ----
    __threadfence();
    if (tid == 0) s_rank = atomicAdd(&g_ctr, 1);
    __syncthreads();
    if (s_rank == NCTAS - 1) {
        for (int pair = tid; pair < C_DIM * B_DIM; pair += 256) {
            const float* a = g_acc + pair * 16;
            float invw = (MODE == 0) ? (1.0f / (float)R_DIM) : (1.0f / __ldcg(&g_accw[pair]));
            float s[16], sq = 0.0f;
            #pragma unroll
            for (int o = 0; o < 16; o++) { s[o] = __ldcg(a + o) * invw; sq += s[o] * s[o]; }
            float coef = sq / ((1.0f + sq) * sqrtf(sq));
            float* dst = (MODE == 2) ? (dout + pair * 16) : (g_out[MODE] + pair * 16);
            #pragma unroll
            for (int o = 0; o < 16; o++) dst[o] = coef * s[o];
        }
        __syncthreads();
        for (int idx = tid; idx < C_DIM * B_DIM * 16; idx += 256) g_acc[idx] = 0.0f;
        for (int idx = tid; idx < C_DIM * B_DIM; idx += 256) g_accw[idx] = 0.0f;
        if (tid == 0) g_ctr = 0;
    }
}

extern "C" void kernel_launch(void* const* d_in, const int* in_sizes, int n_in,
                              void* d_out, int out_size) {
    const float* x = (const float*)d_in[0];          // [64, 6912, 8]
    const float* W = (const float*)d_in[1];          // [10, 6912, 8, 16]
    float* out = (float*)d_out;                      // [10, 64, 1, 1, 16]

    dim3 tgrid(R_DIM * 2 / 32, B_DIM / 32);          // (432, 2)
    k_transpose<<<tgrid, dim3(32, 8)>>>(reinterpret_cast<const float4*>(x));

    dim3 grid(R_DIM / R_BLK, C_DIM);                 // (108, 10)
    k_pass<0><<<grid, 256>>>(W, nullptr);
    k_pass<1><<<grid, 256>>>(W, nullptr);
    k_pass<2><<<grid, 256>>>(W, out);
}